// round 9
// baseline (speedup 1.0000x reference)
#include <cuda_runtime.h>
#include <cstdint>

typedef unsigned long long ull;

#define SEQ    512
#define BATCH  128
#define INPUT  128
#define HIDDEN 512
#define CLUSTER 8
#define THREADS 512

// ---- recurrent smem layout (bytes) ----
// W slice  [16 kq][32 k][64 n] fp32                    131072
// hc compact h: [par 2][k 512][b 8] fp32                32768 (16384 each)
// staging:  [par 2][512 vals] fp32                       4096
// scr partials: [kq 16][n 64][b 8] fp32                 32768
// mbarriers: [par 2] x 8B                                  16
#define HC_OFF   131072
#define STG_OFF  163840
#define SCR_OFF  167936
#define MB_OFF   200704
#define SMEM_BYTES 200768
#define EXCH_BYTES 16384u    // per step: 8 ranks x 2KB

// ---------------------------------------------------------------------------
// Phase 1: proj[row,n] = sum_k input[row,k] * W_in[n,k] -> d_out
// ---------------------------------------------------------------------------
__global__ __launch_bounds__(256) void proj_kernel(
    const float* __restrict__ A, const float* __restrict__ W,
    float* __restrict__ C)
{
    __shared__ float As[64][65];
    __shared__ float Bs[64][65];
    const int tid = threadIdx.x, tx = tid & 15, ty = tid >> 4;
    const int row0 = blockIdx.x * 64, n0 = blockIdx.y * 64;
    float acc[4][4] = {};
    for (int k0 = 0; k0 < INPUT; k0 += 64) {
        #pragma unroll
        for (int i = 0; i < 16; i++) {
            int e = tid + i * 256, r = e >> 6, kk = e & 63;
            As[kk][r] = A[(row0 + r) * INPUT + k0 + kk];
            Bs[kk][r] = W[(n0 + r) * INPUT + k0 + kk];
        }
        __syncthreads();
        #pragma unroll 8
        for (int k = 0; k < 64; k++) {
            float a[4], b[4];
            #pragma unroll
            for (int i = 0; i < 4; i++) a[i] = As[k][ty * 4 + i];
            #pragma unroll
            for (int j = 0; j < 4; j++) b[j] = Bs[k][tx * 4 + j];
            #pragma unroll
            for (int i = 0; i < 4; i++)
                #pragma unroll
                for (int j = 0; j < 4; j++) acc[i][j] += a[i] * b[j];
        }
        __syncthreads();
    }
    #pragma unroll
    for (int i = 0; i < 4; i++) {
        int row = row0 + ty * 4 + i;
        #pragma unroll
        for (int j = 0; j < 4; j++)
            C[row * HIDDEN + n0 + tx * 4 + j] = acc[i][j];
    }
}

// ---- helpers ---------------------------------------------------------------
__device__ __forceinline__ void fma2(ull& d, ull a, ull b) {
    asm("fma.rn.f32x2 %0, %1, %2, %0;" : "+l"(d) : "l"(a), "l"(b));
}
__device__ __forceinline__ ull pk(float lo, float hi) {
    ull d; asm("mov.b64 %0, {%1, %2};" : "=l"(d) : "f"(lo), "f"(hi)); return d;
}
__device__ __forceinline__ uint32_t s2u(const void* p) {
    uint32_t a;
    asm("{ .reg .u64 t; cvta.to.shared.u64 t, %1; cvt.u32.u64 %0, t; }" : "=r"(a) : "l"(p));
    return a;
}

#define MB_WAIT(mb, ph) do {                                                    \
    uint32_t _done;                                                             \
    asm volatile("{\n\t.reg .pred p;\n\t"                                       \
        "mbarrier.try_wait.parity.acquire.cluster.shared::cta.b64 p, [%1], %2;\n\t" \
        "selp.b32 %0, 1, 0, p;\n\t}"                                            \
        : "=r"(_done) : "r"(mb), "r"(ph) : "memory");                           \
    while (!_done) {                                                            \
        asm volatile("{\n\t.reg .pred p;\n\t"                                   \
            "mbarrier.try_wait.parity.acquire.cluster.shared::cta.b64 p, [%1], %2, 0x989680;\n\t" \
            "selp.b32 %0, 1, 0, p;\n\t}"                                        \
            : "=r"(_done) : "r"(mb), "r"(ph) : "memory");                       \
    }                                                                           \
} while (0)

#define MB_ARM(mb)                                                              \
    asm volatile("mbarrier.arrive.expect_tx.shared.b64 _, [%0], %1;"            \
                 :: "r"(mb), "r"(EXCH_BYTES) : "memory")

#define BULK_CLUSTER(dst, src, bytes, mb)                                       \
    asm volatile("cp.async.bulk.shared::cluster.shared::cta.mbarrier::complete_tx::bytes " \
                 "[%0], [%1], %2, [%3];"                                        \
                 :: "r"(dst), "r"(src), "r"(bytes), "r"(mb) : "memory")

// ---------------------------------------------------------------------------
// Phase 2: persistent cluster recurrence, ONE 512-thread engine per CTA.
//   16 clusters x 8 CTAs; rank owns 64 hidden cols; cluster owns 8 batch rows.
//   Matvec: k-split 16, thread tile 4b x 4n over 32 k, f32x2 FMA,
//   h loaded as natural (b,b+1) f32x2 pairs. One sync chain per step:
//   wait -> matvec -> bar -> reduce+update -> stage -> bar -> 8 bulk copies.
// ---------------------------------------------------------------------------
__global__ void __launch_bounds__(THREADS, 1) __cluster_dims__(CLUSTER, 1, 1)
recurrent_kernel(const float* __restrict__ Whid,
                 const float* __restrict__ noise,
                 float* __restrict__ out, int has_tail)
{
    extern __shared__ float sm[];
    const uint32_t sbase = s2u(sm);

    const int tid = threadIdx.x;
    uint32_t rank;
    asm("mov.u32 %0, %%cluster_ctarank;" : "=r"(rank));
    const int n0r   = (int)rank * 64;
    const int bbase = (blockIdx.x >> 3) * 8;

    // ---- load W slice transposed: Ws[k*64+n] = Whid[n0r+n][k] ----
    for (int e2 = tid; e2 < 64 * 128; e2 += THREADS) {
        int n = e2 >> 7, kq4 = e2 & 127;
        float4 v = reinterpret_cast<const float4*>(Whid)[(n0r + n) * 128 + kq4];
        sm[(4 * kq4 + 0) * 64 + n] = v.x;
        sm[(4 * kq4 + 1) * 64 + n] = v.y;
        sm[(4 * kq4 + 2) * 64 + n] = v.z;
        sm[(4 * kq4 + 3) * 64 + n] = v.w;
    }
    // ---- zero parity-0 h buffer (h0 = 0 -> relu = 0) ----
    for (int i = tid; i < 4096; i += THREADS)
        sm[HC_OFF / 4 + i] = 0.0f;
    // ---- init + pre-arm both mbarriers ----
    if (tid == 0) {
        #pragma unroll
        for (int m = 0; m < 2; m++) {
            uint32_t mb = sbase + MB_OFF + m * 8;
            asm volatile("mbarrier.init.shared.b64 [%0], %1;" :: "r"(mb), "r"(1u) : "memory");
        }
        asm volatile("fence.proxy.async.shared::cta;" ::: "memory");
        #pragma unroll
        for (int m = 0; m < 2; m++) MB_ARM(sbase + MB_OFF + m * 8);
    }
    __syncthreads();
    asm volatile("barrier.cluster.arrive.aligned;" ::: "memory");
    asm volatile("barrier.cluster.wait.aligned;"   ::: "memory");

    // ---- matvec mapping: kq (16 x 32k) x bg (2 x 4b) x ng (16 x 4n) ----
    const int kq = tid >> 5;
    const int bg = (tid >> 4) & 1;
    const int ng = tid & 15;
    const uint32_t wp0 = sbase + (uint32_t)(kq * 8192 + ng * 16);
    // scr layout [kq][n 64][b 8]; this thread's base (n = 4*ng, b = 4*bg)
    const uint32_t scr_st = sbase + SCR_OFF + (uint32_t)(kq * 2048 + ng * 128 + bg * 16);
    // ---- reduce/epilogue mapping: one output (b, col) per thread ----
    const int rn  = tid >> 3;            // 0..63
    const int rb  = tid & 7;             // 0..7
    const int col = n0r + rn;
    const int gb  = bbase + rb;
    const uint32_t scr_rd = sbase + SCR_OFF + (uint32_t)((rn * 8 + rb) * 4);
    const uint32_t mb0 = sbase + MB_OFF;
    const uint32_t mb1 = mb0 + 8;
    // peer CTA smem bases
    uint32_t peer[CLUSTER];
    #pragma unroll
    for (int r = 0; r < CLUSTER; r++)
        asm("mapa.shared::cluster.u32 %0, %1, %2;" : "=r"(peer[r]) : "r"(sbase), "r"(r));
    const uint32_t stg_base = sbase + STG_OFF;
    const uint32_t stg_slot = (uint32_t)((rn * 8 + rb) * 4);   // [n][b] = dest [k][b]

    float rh = 0.0f;
    int ph0 = 0, ph1 = 0;

    for (int s = 0; s < SEQ; s++) {
        const int ibuf = s & 1;
        if (s > 0) {
            uint32_t mb = ibuf ? mb1 : mb0;
            int& ph = ibuf ? ph1 : ph0;
            MB_WAIT(mb, ph);
            if (tid == 0) MB_ARM(mb);    // re-arm for step s+2
            ph ^= 1;
        }
        // prefetch proj (in d_out) + noise for the epilogue
        float* optr = out + ((size_t)s * BATCH + gb) * HIDDEN + col;
        float x  = *optr;
        float nz = __ldg(&noise[(size_t)s * HIDDEN + col]);

        // ---- matvec over this thread's 32-k slice, 4b x 4n ----
        const uint32_t hp0 = sbase + (uint32_t)(HC_OFF + ibuf * 16384 + kq * 1024 + bg * 16);
        ull a00 = 0, a01 = 0, a02 = 0, a03 = 0;   // b-pair 0 (b, b+1), n..n+3
        ull a10 = 0, a11 = 0, a12 = 0, a13 = 0;   // b-pair 1 (b+2, b+3)
        #pragma unroll 8
        for (int k = 0; k < 32; k++) {
            ull hp01, hp23;
            float w0, w1, w2, w3;
            asm("ld.shared.v2.u64 {%0,%1}, [%2];"
                : "=l"(hp01), "=l"(hp23) : "r"(hp0 + (uint32_t)(k * 32)));
            asm("ld.shared.v4.f32 {%0,%1,%2,%3}, [%4];"
                : "=f"(w0), "=f"(w1), "=f"(w2), "=f"(w3) : "r"(wp0 + (uint32_t)(k * 256)));
            ull wd0 = pk(w0, w0), wd1 = pk(w1, w1);
            ull wd2 = pk(w2, w2), wd3 = pk(w3, w3);
            fma2(a00, hp01, wd0); fma2(a01, hp01, wd1);
            fma2(a02, hp01, wd2); fma2(a03, hp01, wd3);
            fma2(a10, hp23, wd0); fma2(a11, hp23, wd1);
            fma2(a12, hp23, wd2); fma2(a13, hp23, wd3);
        }
        // scr[kq][n][b]: (b,b+1) pairs are contiguous -> st.shared.u64
        asm volatile("st.shared.u64 [%0],      %1;" :: "r"(scr_st),       "l"(a00));
        asm volatile("st.shared.u64 [%0+32],   %1;" :: "r"(scr_st),       "l"(a01));
        asm volatile("st.shared.u64 [%0+64],   %1;" :: "r"(scr_st),       "l"(a02));
        asm volatile("st.shared.u64 [%0+96],   %1;" :: "r"(scr_st),       "l"(a03));
        asm volatile("st.shared.u64 [%0+8],    %1;" :: "r"(scr_st),       "l"(a10));
        asm volatile("st.shared.u64 [%0+40],   %1;" :: "r"(scr_st),       "l"(a11));
        asm volatile("st.shared.u64 [%0+72],   %1;" :: "r"(scr_st),       "l"(a12));
        asm volatile("st.shared.u64 [%0+104],  %1;" :: "r"(scr_st),       "l"(a13));

        __syncthreads();   // matvec partials visible

        // ---- reduce 16 k-partials + state update ----
        float acc = 0.0f;
        #pragma unroll
        for (int q = 0; q < 16; q++) {
            float v;
            asm("ld.shared.f32 %0, [%1];" : "=f"(v) : "r"(scr_rd + (uint32_t)(q * 2048)));
            acc += v;
        }
        float hn = 0.5f * rh + 0.5f * (acc + x + nz);
        rh = hn;
        *optr = hn;

        if (s < SEQ - 1) {
            // stage compact relu(h_new) (parity of NEXT step)
            float rv = fmaxf(hn, 0.0f);
            uint32_t stg = stg_base + (uint32_t)((ibuf ^ 1) * 2048) + stg_slot;
            asm volatile("st.shared.f32 [%0], %1;" :: "r"(stg), "f"(rv) : "memory");

            __syncthreads();   // staging complete; also protects scr/h WAR

            // ---- 8 threads issue the 8 bulk copies (2KB each) ----
            if (tid < 8) {
                asm volatile("fence.proxy.async.shared::cta;" ::: "memory");
                uint32_t src    = stg_base + (uint32_t)((ibuf ^ 1) * 2048);
                uint32_t dstoff = (uint32_t)(HC_OFF + (ibuf ^ 1) * 16384 + (int)rank * 2048);
                uint32_t mboff  = (uint32_t)(MB_OFF + (ibuf ^ 1) * 8);
                BULK_CLUSTER(peer[tid] + dstoff, src, 2048u, peer[tid] + mboff);
            }
        }
    }

    // ---- fused tail: final hidden state ----
    if (has_tail)
        out[(size_t)SEQ * BATCH * HIDDEN + (size_t)gb * HIDDEN + col] = rh;

    // keep smem alive until all cluster peers are done
    asm volatile("barrier.cluster.arrive.aligned;" ::: "memory");
    asm volatile("barrier.cluster.wait.aligned;"   ::: "memory");
}

// ---------------------------------------------------------------------------
extern "C" void kernel_launch(void* const* d_in, const int* in_sizes, int n_in,
                              void* d_out, int out_size)
{
    const float* input = (const float*)d_in[0];
    const float* W_in  = (const float*)d_in[1];
    const float* W_hid = (const float*)d_in[2];
    const float* noise = (const float*)d_in[3];
    float* out = (float*)d_out;

    cudaFuncSetAttribute(recurrent_kernel,
                         cudaFuncAttributeMaxDynamicSharedMemorySize, SMEM_BYTES);

    dim3 grid((SEQ * BATCH) / 64, HIDDEN / 64);
    proj_kernel<<<grid, 256>>>(input, W_in, out);

    int has_tail = (out_size >= SEQ * BATCH * HIDDEN + BATCH * HIDDEN) ? 1 : 0;
    recurrent_kernel<<<128, THREADS, SMEM_BYTES>>>(W_hid, noise, out, has_tail);
}